// round 8
// baseline (speedup 1.0000x reference)
#include <cuda_runtime.h>
#include <cuda_bf16.h>
#include <stdint.h>
#include <math.h>

#define BN 4
#define CN 64
#define HN 128
#define WN 128
#define SN (HN*WN)      // 16384
#define NP (BN*SN)      // 65536

// Scratch (device globals; no allocations allowed)
__device__ float g_y1[NP*CN];   // layer-1 output, NCHW
__device__ float g_rfh[NP];     // rf_h / 2
__device__ float g_rfw[NP];     // rf_w / 2

// ---------------- smem layout (dynamic) ----------------
// B tiles: [9 taps][64 o rows x 64 c cols] bf16, SW128-swizzled, 8KB/tap
#define B_HI_OFF 0
#define B_LO_OFF 73728
// A tile:  [128 px rows x 64 c cols] bf16, SW128-swizzled, 16KB each of hi/lo
#define A_HI_OFF 147456
#define A_LO_OFF 163840
#define BIAS_OFF 180224
#define SMEM_TOTAL 180480

__device__ __forceinline__ uint32_t swz(uint32_t off) { return off ^ ((off >> 3) & 0x70); }
__device__ __forceinline__ uint32_t pk2(float a, float b) {
    __nv_bfloat162 t = __floats2bfloat162_rn(a, b);
    return *(uint32_t*)&t;
}

__device__ __forceinline__ void mma_bf16(float& d0, float& d1, float& d2, float& d3,
                                         uint32_t a0, uint32_t a1, uint32_t a2, uint32_t a3,
                                         uint32_t b0, uint32_t b1)
{
    asm volatile("mma.sync.aligned.m16n8k16.row.col.f32.bf16.bf16.f32 "
                 "{%0,%1,%2,%3}, {%4,%5,%6,%7}, {%8,%9}, {%0,%1,%2,%3};"
                 : "+f"(d0), "+f"(d1), "+f"(d2), "+f"(d3)
                 : "r"(a0), "r"(a1), "r"(a2), "r"(a3), "r"(b0), "r"(b1));
}

// ---------------------------------------------------------------------------
// Offset conv (NCHW) — unchanged (known good).
// ---------------------------------------------------------------------------
__global__ __launch_bounds__(256)
void offset_conv(const float* __restrict__ xin,
                 const float* __restrict__ woff,
                 const float* __restrict__ boff,
                 const int* __restrict__ p_lo, const int* __restrict__ p_hi,
                 float* __restrict__ rfh, float* __restrict__ rfw)
{
    __shared__ float sw[CN * 18];
    for (int d = threadIdx.x; d < CN * 18; d += 256) {
        int c = d / 18;
        int k = (d % 18) >> 1;
        int j = d & 1;
        sw[d] = woff[(j * CN + c) * 9 + k];
    }
    __syncthreads();

    int p  = blockIdx.x * 256 + threadIdx.x;
    int b  = p >> 14;
    int hw = p & (SN - 1);
    int h  = hw >> 7;
    int w  = hw & (WN - 1);

    bool hm = h > 0, hp = h < HN - 1, wm = w > 0, wp = w < WN - 1;

    float a0 = boff[0], a1 = boff[1];
    const float* xb = xin + (size_t)b * CN * SN;

    #pragma unroll 2
    for (int c = 0; c < CN; c++) {
        const float* xc = xb + c * SN + hw;
        float v[9];
        v[4] = xc[0];
        v[1] = hm ? xc[-WN] : 0.f;
        v[7] = hp ? xc[ WN] : 0.f;
        v[3] = wm ? xc[-1] : 0.f;
        v[5] = wp ? xc[ 1] : 0.f;
        v[0] = (hm && wm) ? xc[-WN - 1] : 0.f;
        v[2] = (hm && wp) ? xc[-WN + 1] : 0.f;
        v[6] = (hp && wm) ? xc[ WN - 1] : 0.f;
        v[8] = (hp && wp) ? xc[ WN + 1] : 0.f;
        const float* wc = sw + c * 18;
        #pragma unroll
        for (int k = 0; k < 9; k++) {
            a0 += v[k] * wc[k * 2 + 0];
            a1 += v[k] * wc[k * 2 + 1];
        }
    }

    float lo   = (float)(*p_lo);
    float span = (float)(*p_hi) - lo;
    float s0 = 1.f / (1.f + __expf(-a0));
    float s1 = 1.f / (1.f + __expf(-a1));
    rfh[p] = 0.5f * (lo + span * s0);
    rfw[p] = 0.5f * (lo + span * s1);
}

// ---------------------------------------------------------------------------
// mma.sync ARConv, 1024 threads / 32 warps (round-6 serial phases, reg-lean).
// Warp w: px rows [16*(w&7), +16), o range [16*(w>>3), +16).
// Producers: 8 threads/px x 8 channels each.
// ---------------------------------------------------------------------------
__global__ __launch_bounds__(1024, 1)
void arconv_mma(const float* __restrict__ xin,
                const float* __restrict__ rfh, const float* __restrict__ rfw,
                const float* __restrict__ Wk,      // [O][C][3][3]
                const float* __restrict__ bias,    // [O]
                const float* __restrict__ resid,   // NCHW (mode 1) or null
                float* __restrict__ outp,
                int mode)
{
    extern __shared__ char smem[];
    int tid = threadIdx.x, wid = tid >> 5, lid = tid & 31;
    int g = lid >> 2, t = lid & 3;   // mma quad coords
    int oq = wid >> 3;               // 0..3: which 16-o quarter this warp computes
    int rbase = 16 * (wid & 7);      // px row base for this warp

    // B hi/lo conversion into SW128-swizzled tap tiles [o rows x c cols]
    for (int d = tid; d < 9 * 64 * 64; d += 1024) {
        int tap = d >> 12;
        int o   = (d >> 6) & 63;
        int c   = d & 63;
        float wv = Wk[(o * 64 + c) * 9 + tap];
        __nv_bfloat16 hb = __float2bfloat16(wv);
        float hf = __bfloat162float(hb);
        __nv_bfloat16 lb = __float2bfloat16(wv - hf);
        uint32_t s = tap * 8192 + swz((uint32_t)(o * 128 + c * 2));
        *(__nv_bfloat16*)(smem + B_HI_OFF + s) = hb;
        *(__nv_bfloat16*)(smem + B_LO_OFF + s) = lb;
    }
    if (tid < 64) *(float*)(smem + BIAS_OFF + tid * 4) = bias[tid];
    __syncthreads();

    const float* biasS = (const float*)(smem + BIAS_OFF);

    for (int it = 0; it < 4; it++) {
        int tile = blockIdx.x * 4 + it;
        int p0 = tile * 128;

        // ---- per-pixel sampling geometry (producer role) ----
        int px = tid & 127;
        int cbase = (tid >> 7) * 8;      // 8 producer groups of 8 channels
        int p = p0 + px;
        int b = p >> 14;
        int hw = p & (SN - 1);
        int h = hw >> 7;
        int w = hw & (WN - 1);

        float rh = rfh[p];
        float rw = rfw[p];

        float xsl = (float)w - rw, xsr = (float)w + rw;
        float xl0f = floorf(xsl), xr0f = floorf(xsr);
        float txl = xsl - xl0f, txr = xsr - xr0f;
        int xl0 = min(max((int)xl0f, 0), WN - 1); int xl1 = min(xl0 + 1, WN - 1);
        int xr0 = min(max((int)xr0f, 0), WN - 1); int xr1 = min(xr0 + 1, WN - 1);

        float ysa = (float)h - rh, ysb = (float)h + rh;
        float ya0f = floorf(ysa), yb0f = floorf(ysb);
        float tya = ysa - ya0f, tyb = ysb - yb0f;
        int ya0 = min(max((int)ya0f, 0), HN - 1); int ya1 = min(ya0 + 1, HN - 1);
        int yb0 = min(max((int)yb0f, 0), HN - 1); int yb1 = min(yb0 + 1, HN - 1);

        int oa0 = ya0 * WN, oa1 = ya1 * WN, ohh = h * WN, ob0 = yb0 * WN, ob1 = yb1 * WN;

        const float* xb = xin + (size_t)(b * CN + cbase) * SN;
        uint32_t sbase = (uint32_t)(px * 128 + cbase * 2);

        // mma accumulators: [nb 0..1][c0..c3]  (16 o per warp)
        float acc[2][4];
        #pragma unroll
        for (int nb = 0; nb < 2; nb++)
            #pragma unroll
            for (int j = 0; j < 4; j++) acc[nb][j] = 0.f;

        #pragma unroll 1
        for (int tap = 0; tap < 9; tap++) {
            int ky = (tap >= 6) ? 2 : (tap >= 3) ? 1 : 0;
            int kx = tap - ky * 3;

            int ry0 = (ky == 0) ? oa0 : (ky == 1) ? ohh : ob0;
            int ry1 = (ky == 0) ? oa1 : (ky == 1) ? ohh : ob1;
            float tyv = (ky == 0) ? tya : (ky == 1) ? 0.f : tyb;
            int x0 = (kx == 0) ? xl0 : (kx == 1) ? w : xr0;
            int x1 = (kx == 0) ? xl1 : (kx == 1) ? w : xr1;
            float txv = (kx == 0) ? txl : (kx == 1) ? 0.f : txr;
            bool cy = (ky == 1), cx = (kx == 1);

            // ---- produce: 8 channels per thread ----
            {
                float v[8];
                if (cy && cx) {
                    #pragma unroll
                    for (int j = 0; j < 8; j++) v[j] = xb[(size_t)j * SN + ohh + w];
                } else if (cy) {
                    float q0[8], q1[8];
                    #pragma unroll
                    for (int j = 0; j < 8; j++) {
                        q0[j] = xb[(size_t)j * SN + ohh + x0];
                        q1[j] = xb[(size_t)j * SN + ohh + x1];
                    }
                    #pragma unroll
                    for (int j = 0; j < 8; j++) v[j] = fmaf(txv, q1[j] - q0[j], q0[j]);
                } else if (cx) {
                    float q0[8], q1[8];
                    #pragma unroll
                    for (int j = 0; j < 8; j++) {
                        q0[j] = xb[(size_t)j * SN + ry0 + w];
                        q1[j] = xb[(size_t)j * SN + ry1 + w];
                    }
                    #pragma unroll
                    for (int j = 0; j < 8; j++) v[j] = fmaf(tyv, q1[j] - q0[j], q0[j]);
                } else {
                    // corner tap: two passes of 4 channels to cap reg pressure
                    #pragma unroll
                    for (int ps = 0; ps < 2; ps++) {
                        float a0[4], a1[4], c0[4], c1[4];
                        #pragma unroll
                        for (int j = 0; j < 4; j++) {
                            int jc = ps * 4 + j;
                            a0[j] = xb[(size_t)jc * SN + ry0 + x0];
                            a1[j] = xb[(size_t)jc * SN + ry0 + x1];
                            c0[j] = xb[(size_t)jc * SN + ry1 + x0];
                            c1[j] = xb[(size_t)jc * SN + ry1 + x1];
                        }
                        #pragma unroll
                        for (int j = 0; j < 4; j++) {
                            float t0 = fmaf(txv, a1[j] - a0[j], a0[j]);
                            float t1 = fmaf(txv, c1[j] - c0[j], c0[j]);
                            v[ps * 4 + j] = fmaf(tyv, t1 - t0, t0);
                        }
                    }
                }

                float hf[8], lo[8];
                #pragma unroll
                for (int j = 0; j < 8; j++) {
                    __nv_bfloat16 hb = __float2bfloat16(v[j]);
                    hf[j] = __bfloat162float(hb);
                    lo[j] = v[j] - hf[j];
                }
                uint4 HV, LV;
                HV.x = pk2(hf[0], hf[1]); HV.y = pk2(hf[2], hf[3]);
                HV.z = pk2(hf[4], hf[5]); HV.w = pk2(hf[6], hf[7]);
                LV.x = pk2(lo[0], lo[1]); LV.y = pk2(lo[2], lo[3]);
                LV.z = pk2(lo[4], lo[5]); LV.w = pk2(lo[6], lo[7]);

                uint32_t s = swz(sbase);
                *(uint4*)(smem + A_HI_OFF + s) = HV;
                *(uint4*)(smem + A_LO_OFF + s) = LV;
            }

            __syncthreads();

            // ---- consume: warp computes 16 px x 16 o ----
            {
                uint32_t btap = tap * 8192;
                #pragma unroll
                for (int chunk = 0; chunk < 4; chunk++) {
                    int ck = chunk * 16;
                    uint32_t ar0 = swz((uint32_t)((rbase + g) * 128 + (ck + 2 * t) * 2));
                    uint32_t ar1 = swz((uint32_t)((rbase + g + 8) * 128 + (ck + 2 * t) * 2));
                    uint32_t ac0 = swz((uint32_t)((rbase + g) * 128 + (ck + 2 * t + 8) * 2));
                    uint32_t ac1 = swz((uint32_t)((rbase + g + 8) * 128 + (ck + 2 * t + 8) * 2));
                    uint32_t ah0 = *(const uint32_t*)(smem + A_HI_OFF + ar0);
                    uint32_t ah1 = *(const uint32_t*)(smem + A_HI_OFF + ar1);
                    uint32_t ah2 = *(const uint32_t*)(smem + A_HI_OFF + ac0);
                    uint32_t ah3 = *(const uint32_t*)(smem + A_HI_OFF + ac1);
                    uint32_t al0 = *(const uint32_t*)(smem + A_LO_OFF + ar0);
                    uint32_t al1 = *(const uint32_t*)(smem + A_LO_OFF + ar1);
                    uint32_t al2 = *(const uint32_t*)(smem + A_LO_OFF + ac0);
                    uint32_t al3 = *(const uint32_t*)(smem + A_LO_OFF + ac1);

                    #pragma unroll
                    for (int nb = 0; nb < 2; nb++) {
                        int o = oq * 16 + nb * 8 + g;
                        uint32_t br0 = swz((uint32_t)(o * 128 + (ck + 2 * t) * 2));
                        uint32_t br1 = swz((uint32_t)(o * 128 + (ck + 2 * t + 8) * 2));
                        uint32_t bh0 = *(const uint32_t*)(smem + B_HI_OFF + btap + br0);
                        uint32_t bh1 = *(const uint32_t*)(smem + B_HI_OFF + btap + br1);
                        uint32_t bl0 = *(const uint32_t*)(smem + B_LO_OFF + btap + br0);
                        uint32_t bl1 = *(const uint32_t*)(smem + B_LO_OFF + btap + br1);

                        mma_bf16(acc[nb][0], acc[nb][1], acc[nb][2], acc[nb][3],
                                 ah0, ah1, ah2, ah3, bh0, bh1);
                        mma_bf16(acc[nb][0], acc[nb][1], acc[nb][2], acc[nb][3],
                                 al0, al1, al2, al3, bh0, bh1);
                        mma_bf16(acc[nb][0], acc[nb][1], acc[nb][2], acc[nb][3],
                                 ah0, ah1, ah2, ah3, bl0, bl1);
                    }
                }
            }
            __syncthreads();   // protect A before next tap's produce
        }

        // ---- epilogue: D fragment -> NCHW (regs only; no barrier needed) ----
        {
            int px0 = p0 + rbase + g;
            int px1 = px0 + 8;
            int b0i = px0 >> 14, hw0 = px0 & (SN - 1);
            int b1i = px1 >> 14, hw1 = px1 & (SN - 1);
            #pragma unroll
            for (int nb = 0; nb < 2; nb++) {
                int o0 = oq * 16 + nb * 8 + 2 * t;
                int o1 = o0 + 1;
                size_t i00 = ((size_t)(b0i * CN + o0)) * SN + hw0;
                size_t i01 = ((size_t)(b0i * CN + o1)) * SN + hw0;
                size_t i10 = ((size_t)(b1i * CN + o0)) * SN + hw1;
                size_t i11 = ((size_t)(b1i * CN + o1)) * SN + hw1;
                float v00 = acc[nb][0] + biasS[o0];
                float v01 = acc[nb][1] + biasS[o1];
                float v10 = acc[nb][2] + biasS[o0];
                float v11 = acc[nb][3] + biasS[o1];
                if (mode == 0) {
                    outp[i00] = fmaxf(v00, 0.f);
                    outp[i01] = fmaxf(v01, 0.f);
                    outp[i10] = fmaxf(v10, 0.f);
                    outp[i11] = fmaxf(v11, 0.f);
                } else {
                    outp[i00] = v00 + resid[i00];
                    outp[i01] = v01 + resid[i01];
                    outp[i10] = v10 + resid[i10];
                    outp[i11] = v11 + resid[i11];
                }
            }
        }
    }
}

// ---------------------------------------------------------------------------
extern "C" void kernel_launch(void* const* d_in, const int* in_sizes, int n_in,
                              void* d_out, int out_size)
{
    const float* x     = (const float*)d_in[0];
    const float* woff1 = (const float*)d_in[1];
    const float* boff1 = (const float*)d_in[2];
    const float* W1    = (const float*)d_in[3];
    const float* b1    = (const float*)d_in[4];
    const float* woff2 = (const float*)d_in[5];
    const float* boff2 = (const float*)d_in[6];
    const float* W2    = (const float*)d_in[7];
    const float* b2    = (const float*)d_in[8];
    const int*   lo    = (const int*)d_in[10];
    const int*   hi    = (const int*)d_in[11];
    float* out = (float*)d_out;

    float *y1, *rfh, *rfw;
    cudaGetSymbolAddress((void**)&y1,  g_y1);
    cudaGetSymbolAddress((void**)&rfh, g_rfh);
    cudaGetSymbolAddress((void**)&rfw, g_rfw);

    cudaFuncSetAttribute(arconv_mma, cudaFuncAttributeMaxDynamicSharedMemorySize, SMEM_TOTAL);

    // Layer 1
    offset_conv<<<NP / 256, 256>>>(x, woff1, boff1, lo, hi, rfh, rfw);
    arconv_mma<<<128, 1024, SMEM_TOTAL>>>(x, rfh, rfw, W1, b1, nullptr, y1, 0);

    // Layer 2 (+ residual)
    offset_conv<<<NP / 256, 256>>>(y1, woff2, boff2, lo, hi, rfh, rfw);
    arconv_mma<<<128, 1024, SMEM_TOTAL>>>(y1, rfh, rfw, W2, b2, x, out, 1);
}

// round 9
// speedup vs baseline: 1.1256x; 1.1256x over previous
#include <cuda_runtime.h>
#include <cuda_bf16.h>
#include <stdint.h>
#include <math.h>

#define BN 4
#define CN 64
#define HN 128
#define WN 128
#define SN (HN*WN)      // 16384
#define NP (BN*SN)      // 65536

// Scratch (device globals; no allocations allowed)
__device__ float g_y1[NP*CN];   // layer-1 output, NCHW
__device__ float g_rfh[NP];     // rf_h / 2
__device__ float g_rfw[NP];     // rf_w / 2

// ---------------- smem layout (dynamic) ----------------
// B tiles: [9 taps][64 o rows x 64 c cols] bf16, SW128-swizzled, 8KB/tap
#define B_HI_OFF 0
#define B_LO_OFF 73728
// A tiles: [2 tiles][128 px x 64 c] bf16 hi and lo, SW128-swizzled, 16KB each
#define A_HI_OFF 147456
#define A_LO_OFF 180224
#define BIAS_OFF 212992
#define SMEM_TOTAL 213504

__device__ __forceinline__ uint32_t swz(uint32_t off) { return off ^ ((off >> 3) & 0x70); }
__device__ __forceinline__ uint32_t pk2(float a, float b) {
    __nv_bfloat162 t = __floats2bfloat162_rn(a, b);
    return *(uint32_t*)&t;
}

__device__ __forceinline__ void mma_bf16(float& d0, float& d1, float& d2, float& d3,
                                         uint32_t a0, uint32_t a1, uint32_t a2, uint32_t a3,
                                         uint32_t b0, uint32_t b1)
{
    asm volatile("mma.sync.aligned.m16n8k16.row.col.f32.bf16.bf16.f32 "
                 "{%0,%1,%2,%3}, {%4,%5,%6,%7}, {%8,%9}, {%0,%1,%2,%3};"
                 : "+f"(d0), "+f"(d1), "+f"(d2), "+f"(d3)
                 : "r"(a0), "r"(a1), "r"(a2), "r"(a3), "r"(b0), "r"(b1));
}

// ---------------------------------------------------------------------------
// Offset conv (NCHW) — unchanged (known good).
// ---------------------------------------------------------------------------
__global__ __launch_bounds__(256)
void offset_conv(const float* __restrict__ xin,
                 const float* __restrict__ woff,
                 const float* __restrict__ boff,
                 const int* __restrict__ p_lo, const int* __restrict__ p_hi,
                 float* __restrict__ rfh, float* __restrict__ rfw)
{
    __shared__ float sw[CN * 18];
    for (int d = threadIdx.x; d < CN * 18; d += 256) {
        int c = d / 18;
        int k = (d % 18) >> 1;
        int j = d & 1;
        sw[d] = woff[(j * CN + c) * 9 + k];
    }
    __syncthreads();

    int p  = blockIdx.x * 256 + threadIdx.x;
    int b  = p >> 14;
    int hw = p & (SN - 1);
    int h  = hw >> 7;
    int w  = hw & (WN - 1);

    bool hm = h > 0, hp = h < HN - 1, wm = w > 0, wp = w < WN - 1;

    float a0 = boff[0], a1 = boff[1];
    const float* xb = xin + (size_t)b * CN * SN;

    #pragma unroll 2
    for (int c = 0; c < CN; c++) {
        const float* xc = xb + c * SN + hw;
        float v[9];
        v[4] = xc[0];
        v[1] = hm ? xc[-WN] : 0.f;
        v[7] = hp ? xc[ WN] : 0.f;
        v[3] = wm ? xc[-1] : 0.f;
        v[5] = wp ? xc[ 1] : 0.f;
        v[0] = (hm && wm) ? xc[-WN - 1] : 0.f;
        v[2] = (hm && wp) ? xc[-WN + 1] : 0.f;
        v[6] = (hp && wm) ? xc[ WN - 1] : 0.f;
        v[8] = (hp && wp) ? xc[ WN + 1] : 0.f;
        const float* wc = sw + c * 18;
        #pragma unroll
        for (int k = 0; k < 9; k++) {
            a0 += v[k] * wc[k * 2 + 0];
            a1 += v[k] * wc[k * 2 + 1];
        }
    }

    float lo   = (float)(*p_lo);
    float span = (float)(*p_hi) - lo;
    float s0 = 1.f / (1.f + __expf(-a0));
    float s1 = 1.f / (1.f + __expf(-a1));
    rfh[p] = 0.5f * (lo + span * s0);
    rfw[p] = 0.5f * (lo + span * s1);
}

// ---------------------------------------------------------------------------
// mma.sync ARConv, 512 threads / 16 warps, TWO 128-px tiles per phase so each
// B fragment load is reused across both tiles (33% less smem traffic/tile).
// Warp w: px rows [16*(w&7), +16) of each tile, o range [32*(w>>3), +32).
// Producers: 4 threads/px x 16 channels, per tile sequentially.
// ---------------------------------------------------------------------------
__global__ __launch_bounds__(512, 1)
void arconv_mma(const float* __restrict__ xin,
                const float* __restrict__ rfh, const float* __restrict__ rfw,
                const float* __restrict__ Wk,      // [O][C][3][3]
                const float* __restrict__ bias,    // [O]
                const float* __restrict__ resid,   // NCHW (mode 1) or null
                float* __restrict__ outp,
                int mode)
{
    extern __shared__ char smem[];
    int tid = threadIdx.x, wid = tid >> 5, lid = tid & 31;
    int g = lid >> 2, t = lid & 3;   // mma quad coords
    int ohalf = wid >> 3;            // which 32-o half this warp computes
    int rbase = 16 * (wid & 7);      // px row base for this warp

    // B hi/lo conversion into SW128-swizzled tap tiles [o rows x c cols]
    for (int d = tid; d < 9 * 64 * 64; d += 512) {
        int tap = d >> 12;
        int o   = (d >> 6) & 63;
        int c   = d & 63;
        float wv = Wk[(o * 64 + c) * 9 + tap];
        __nv_bfloat16 hb = __float2bfloat16(wv);
        float hf = __bfloat162float(hb);
        __nv_bfloat16 lb = __float2bfloat16(wv - hf);
        uint32_t s = tap * 8192 + swz((uint32_t)(o * 128 + c * 2));
        *(__nv_bfloat16*)(smem + B_HI_OFF + s) = hb;
        *(__nv_bfloat16*)(smem + B_LO_OFF + s) = lb;
    }
    if (tid < 64) *(float*)(smem + BIAS_OFF + tid * 4) = bias[tid];
    __syncthreads();

    const float* biasS = (const float*)(smem + BIAS_OFF);

    int px = tid & 127;
    int cbase = (tid >> 7) * 16;     // 4 producer groups of 16 channels
    uint32_t sbase = swz((uint32_t)(px * 128 + cbase * 2));
    uint32_t sbase2 = swz((uint32_t)(px * 128 + cbase * 2 + 16));

    for (int pp = 0; pp < 2; pp++) {
        int tile0 = (blockIdx.x * 2 + pp) * 2;   // tiles tile0, tile0+1

        // per-tile pixel geometry (minimal persistent state)
        int   pT[2], hT[2], wT[2];
        float rhT[2], rwT[2];
        const float* xbT[2];
        #pragma unroll
        for (int tt = 0; tt < 2; tt++) {
            int p = (tile0 + tt) * 128 + px;
            pT[tt] = p;
            int b = p >> 14;
            int hw = p & (SN - 1);
            hT[tt] = hw >> 7;
            wT[tt] = hw & (WN - 1);
            rhT[tt] = rfh[p];
            rwT[tt] = rfw[p];
            xbT[tt] = xin + (size_t)(b * CN + cbase) * SN;
        }

        // acc[tile][nb][4]
        float acc[2][4][4];
        #pragma unroll
        for (int tt = 0; tt < 2; tt++)
            #pragma unroll
            for (int nb = 0; nb < 4; nb++)
                #pragma unroll
                for (int j = 0; j < 4; j++) acc[tt][nb][j] = 0.f;

        #pragma unroll 1
        for (int tap = 0; tap < 9; tap++) {
            int ky = (tap >= 6) ? 2 : (tap >= 3) ? 1 : 0;
            int kx = tap - ky * 3;
            bool cy = (ky == 1), cx = (kx == 1);

            // ---- produce A for BOTH tiles ----
            #pragma unroll 1
            for (int tt = 0; tt < 2; tt++) {
                int h = hT[tt], w = wT[tt];
                float rh = rhT[tt], rw = rwT[tt];

                // tap-specific geometry (recomputed: keeps regs low)
                int ry0, ry1; float tyv;
                if (cy) { ry0 = ry1 = h * WN; tyv = 0.f; }
                else {
                    float ys = (ky == 0) ? (float)h - rh : (float)h + rh;
                    float y0f = floorf(ys); tyv = ys - y0f;
                    int y0 = min(max((int)y0f, 0), HN - 1);
                    int y1 = min(y0 + 1, HN - 1);
                    ry0 = y0 * WN; ry1 = y1 * WN;
                }
                int x0, x1; float txv;
                if (cx) { x0 = x1 = w; txv = 0.f; }
                else {
                    float xs = (kx == 0) ? (float)w - rw : (float)w + rw;
                    float x0f = floorf(xs); txv = xs - x0f;
                    x0 = min(max((int)x0f, 0), WN - 1);
                    x1 = min(x0 + 1, WN - 1);
                }

                const float* xb = xbT[tt];
                char* Ah = smem + A_HI_OFF + tt * 16384;
                char* Al = smem + A_LO_OFF + tt * 16384;

                #pragma unroll 1
                for (int cg = 0; cg < 2; cg++) {
                    const float* xc = xb + (size_t)(cg * 8) * SN;
                    float v[8];
                    if (cy && cx) {
                        #pragma unroll
                        for (int j = 0; j < 8; j++) v[j] = xc[(size_t)j * SN + ry0 + w];
                    } else if (cy) {
                        float q0[8], q1[8];
                        #pragma unroll
                        for (int j = 0; j < 8; j++) {
                            q0[j] = xc[(size_t)j * SN + ry0 + x0];
                            q1[j] = xc[(size_t)j * SN + ry0 + x1];
                        }
                        #pragma unroll
                        for (int j = 0; j < 8; j++) v[j] = fmaf(txv, q1[j] - q0[j], q0[j]);
                    } else if (cx) {
                        float q0[8], q1[8];
                        #pragma unroll
                        for (int j = 0; j < 8; j++) {
                            q0[j] = xc[(size_t)j * SN + ry0 + w];
                            q1[j] = xc[(size_t)j * SN + ry1 + w];
                        }
                        #pragma unroll
                        for (int j = 0; j < 8; j++) v[j] = fmaf(tyv, q1[j] - q0[j], q0[j]);
                    } else {
                        float a0[8], a1[8], c0[8], c1[8];
                        #pragma unroll
                        for (int j = 0; j < 8; j++) {
                            a0[j] = xc[(size_t)j * SN + ry0 + x0];
                            a1[j] = xc[(size_t)j * SN + ry0 + x1];
                            c0[j] = xc[(size_t)j * SN + ry1 + x0];
                            c1[j] = xc[(size_t)j * SN + ry1 + x1];
                        }
                        #pragma unroll
                        for (int j = 0; j < 8; j++) {
                            float t0 = fmaf(txv, a1[j] - a0[j], a0[j]);
                            float t1 = fmaf(txv, c1[j] - c0[j], c0[j]);
                            v[j] = fmaf(tyv, t1 - t0, t0);
                        }
                    }

                    float hf[8], lo[8];
                    #pragma unroll
                    for (int j = 0; j < 8; j++) {
                        __nv_bfloat16 hb = __float2bfloat16(v[j]);
                        hf[j] = __bfloat162float(hb);
                        lo[j] = v[j] - hf[j];
                    }
                    uint4 HV, LV;
                    HV.x = pk2(hf[0], hf[1]); HV.y = pk2(hf[2], hf[3]);
                    HV.z = pk2(hf[4], hf[5]); HV.w = pk2(hf[6], hf[7]);
                    LV.x = pk2(lo[0], lo[1]); LV.y = pk2(lo[2], lo[3]);
                    LV.z = pk2(lo[4], lo[5]); LV.w = pk2(lo[6], lo[7]);

                    uint32_t s = cg ? sbase2 : sbase;
                    *(uint4*)(Ah + s) = HV;
                    *(uint4*)(Al + s) = LV;
                }
            }

            __syncthreads();

            // ---- consume: each B fragment reused for BOTH tiles ----
            {
                uint32_t btap = tap * 8192;
                const char* A0h = smem + A_HI_OFF;
                const char* A0l = smem + A_LO_OFF;
                const char* A1h = smem + A_HI_OFF + 16384;
                const char* A1l = smem + A_LO_OFF + 16384;

                #pragma unroll
                for (int chunk = 0; chunk < 4; chunk++) {
                    int ck = chunk * 16;
                    uint32_t ar0 = swz((uint32_t)((rbase + g) * 128 + (ck + 2 * t) * 2));
                    uint32_t ar1 = swz((uint32_t)((rbase + g + 8) * 128 + (ck + 2 * t) * 2));
                    uint32_t ac0 = swz((uint32_t)((rbase + g) * 128 + (ck + 2 * t + 8) * 2));
                    uint32_t ac1 = swz((uint32_t)((rbase + g + 8) * 128 + (ck + 2 * t + 8) * 2));

                    uint32_t ah0 = *(const uint32_t*)(A0h + ar0);
                    uint32_t ah1 = *(const uint32_t*)(A0h + ar1);
                    uint32_t ah2 = *(const uint32_t*)(A0h + ac0);
                    uint32_t ah3 = *(const uint32_t*)(A0h + ac1);
                    uint32_t al0 = *(const uint32_t*)(A0l + ar0);
                    uint32_t al1 = *(const uint32_t*)(A0l + ar1);
                    uint32_t al2 = *(const uint32_t*)(A0l + ac0);
                    uint32_t al3 = *(const uint32_t*)(A0l + ac1);

                    uint32_t bh0v = *(const uint32_t*)(A1h + ar0);
                    uint32_t bh1v = *(const uint32_t*)(A1h + ar1);
                    uint32_t bh2v = *(const uint32_t*)(A1h + ac0);
                    uint32_t bh3v = *(const uint32_t*)(A1h + ac1);
                    uint32_t bl0v = *(const uint32_t*)(A1l + ar0);
                    uint32_t bl1v = *(const uint32_t*)(A1l + ar1);
                    uint32_t bl2v = *(const uint32_t*)(A1l + ac0);
                    uint32_t bl3v = *(const uint32_t*)(A1l + ac1);

                    #pragma unroll
                    for (int nb = 0; nb < 4; nb++) {
                        int o = ohalf * 32 + nb * 8 + g;
                        uint32_t br0 = swz((uint32_t)(o * 128 + (ck + 2 * t) * 2));
                        uint32_t br1 = swz((uint32_t)(o * 128 + (ck + 2 * t + 8) * 2));
                        uint32_t wh0 = *(const uint32_t*)(smem + B_HI_OFF + btap + br0);
                        uint32_t wh1 = *(const uint32_t*)(smem + B_HI_OFF + btap + br1);
                        uint32_t wl0 = *(const uint32_t*)(smem + B_LO_OFF + btap + br0);
                        uint32_t wl1 = *(const uint32_t*)(smem + B_LO_OFF + btap + br1);

                        mma_bf16(acc[0][nb][0], acc[0][nb][1], acc[0][nb][2], acc[0][nb][3],
                                 ah0, ah1, ah2, ah3, wh0, wh1);
                        mma_bf16(acc[0][nb][0], acc[0][nb][1], acc[0][nb][2], acc[0][nb][3],
                                 al0, al1, al2, al3, wh0, wh1);
                        mma_bf16(acc[0][nb][0], acc[0][nb][1], acc[0][nb][2], acc[0][nb][3],
                                 ah0, ah1, ah2, ah3, wl0, wl1);

                        mma_bf16(acc[1][nb][0], acc[1][nb][1], acc[1][nb][2], acc[1][nb][3],
                                 bh0v, bh1v, bh2v, bh3v, wh0, wh1);
                        mma_bf16(acc[1][nb][0], acc[1][nb][1], acc[1][nb][2], acc[1][nb][3],
                                 bl0v, bl1v, bl2v, bl3v, wh0, wh1);
                        mma_bf16(acc[1][nb][0], acc[1][nb][1], acc[1][nb][2], acc[1][nb][3],
                                 bh0v, bh1v, bh2v, bh3v, wl0, wl1);
                    }
                }
            }
            __syncthreads();   // protect A before next tap's produce
        }

        // ---- epilogue: D fragments -> NCHW, both tiles ----
        #pragma unroll
        for (int tt = 0; tt < 2; tt++) {
            int px0 = (tile0 + tt) * 128 + rbase + g;
            int px1 = px0 + 8;
            int b0i = px0 >> 14, hw0 = px0 & (SN - 1);
            int b1i = px1 >> 14, hw1 = px1 & (SN - 1);
            #pragma unroll
            for (int nb = 0; nb < 4; nb++) {
                int o0 = ohalf * 32 + nb * 8 + 2 * t;
                int o1 = o0 + 1;
                size_t i00 = ((size_t)(b0i * CN + o0)) * SN + hw0;
                size_t i01 = ((size_t)(b0i * CN + o1)) * SN + hw0;
                size_t i10 = ((size_t)(b1i * CN + o0)) * SN + hw1;
                size_t i11 = ((size_t)(b1i * CN + o1)) * SN + hw1;
                float v00 = acc[tt][nb][0] + biasS[o0];
                float v01 = acc[tt][nb][1] + biasS[o1];
                float v10 = acc[tt][nb][2] + biasS[o0];
                float v11 = acc[tt][nb][3] + biasS[o1];
                if (mode == 0) {
                    outp[i00] = fmaxf(v00, 0.f);
                    outp[i01] = fmaxf(v01, 0.f);
                    outp[i10] = fmaxf(v10, 0.f);
                    outp[i11] = fmaxf(v11, 0.f);
                } else {
                    outp[i00] = v00 + resid[i00];
                    outp[i01] = v01 + resid[i01];
                    outp[i10] = v10 + resid[i10];
                    outp[i11] = v11 + resid[i11];
                }
            }
        }
    }
}

// ---------------------------------------------------------------------------
extern "C" void kernel_launch(void* const* d_in, const int* in_sizes, int n_in,
                              void* d_out, int out_size)
{
    const float* x     = (const float*)d_in[0];
    const float* woff1 = (const float*)d_in[1];
    const float* boff1 = (const float*)d_in[2];
    const float* W1    = (const float*)d_in[3];
    const float* b1    = (const float*)d_in[4];
    const float* woff2 = (const float*)d_in[5];
    const float* boff2 = (const float*)d_in[6];
    const float* W2    = (const float*)d_in[7];
    const float* b2    = (const float*)d_in[8];
    const int*   lo    = (const int*)d_in[10];
    const int*   hi    = (const int*)d_in[11];
    float* out = (float*)d_out;

    float *y1, *rfh, *rfw;
    cudaGetSymbolAddress((void**)&y1,  g_y1);
    cudaGetSymbolAddress((void**)&rfh, g_rfh);
    cudaGetSymbolAddress((void**)&rfw, g_rfw);

    cudaFuncSetAttribute(arconv_mma, cudaFuncAttributeMaxDynamicSharedMemorySize, SMEM_TOTAL);

    // Layer 1
    offset_conv<<<NP / 256, 256>>>(x, woff1, boff1, lo, hi, rfh, rfw);
    arconv_mma<<<128, 512, SMEM_TOTAL>>>(x, rfh, rfw, W1, b1, nullptr, y1, 0);

    // Layer 2 (+ residual)
    offset_conv<<<NP / 256, 256>>>(y1, woff2, boff2, lo, hi, rfh, rfw);
    arconv_mma<<<128, 512, SMEM_TOTAL>>>(y1, rfh, rfw, W2, b2, x, out, 1);
}

// round 10
// speedup vs baseline: 1.2702x; 1.1285x over previous
#include <cuda_runtime.h>
#include <cuda_bf16.h>
#include <stdint.h>
#include <math.h>

#define BN 4
#define CN 64
#define HN 128
#define WN 128
#define SN (HN*WN)      // 16384
#define NP (BN*SN)      // 65536

// Scratch (device globals; no allocations allowed)
__device__ float g_y1[NP*CN];   // layer-1 output, NCHW
__device__ float g_rfh[NP];     // rf_h / 2
__device__ float g_rfw[NP];     // rf_w / 2

// ---------------- smem layout (dynamic) ----------------
// B tiles: [9 taps][64 o rows x 64 c cols] bf16, SW128-swizzled, 8KB/tap
#define B_HI_OFF 0
#define B_LO_OFF 73728
// A ring: 2 buffers, each {hi 16KB, lo 16KB} : [128 px x 64 c] bf16 SW128
#define A_BASE   147456
#define BIAS_OFF 212992
#define SMEM_TOTAL 213248

// named barriers: full0=1, full1=2, empty0=3, empty1=4 (count 512)
#define BAR_SYNC(id)   asm volatile("bar.sync %0, 512;"   :: "r"(id) : "memory")
#define BAR_ARRIVE(id) asm volatile("bar.arrive %0, 512;" :: "r"(id) : "memory")

__device__ __forceinline__ uint32_t swz(uint32_t off) { return off ^ ((off >> 3) & 0x70); }
__device__ __forceinline__ uint32_t pk2(float a, float b) {
    __nv_bfloat162 t = __floats2bfloat162_rn(a, b);
    return *(uint32_t*)&t;
}

__device__ __forceinline__ void mma_bf16(float& d0, float& d1, float& d2, float& d3,
                                         uint32_t a0, uint32_t a1, uint32_t a2, uint32_t a3,
                                         uint32_t b0, uint32_t b1)
{
    asm volatile("mma.sync.aligned.m16n8k16.row.col.f32.bf16.bf16.f32 "
                 "{%0,%1,%2,%3}, {%4,%5,%6,%7}, {%8,%9}, {%0,%1,%2,%3};"
                 : "+f"(d0), "+f"(d1), "+f"(d2), "+f"(d3)
                 : "r"(a0), "r"(a1), "r"(a2), "r"(a3), "r"(b0), "r"(b1));
}

// ---------------------------------------------------------------------------
// Offset conv (NCHW) — unchanged (known good).
// ---------------------------------------------------------------------------
__global__ __launch_bounds__(256)
void offset_conv(const float* __restrict__ xin,
                 const float* __restrict__ woff,
                 const float* __restrict__ boff,
                 const int* __restrict__ p_lo, const int* __restrict__ p_hi,
                 float* __restrict__ rfh, float* __restrict__ rfw)
{
    __shared__ float sw[CN * 18];
    for (int d = threadIdx.x; d < CN * 18; d += 256) {
        int c = d / 18;
        int k = (d % 18) >> 1;
        int j = d & 1;
        sw[d] = woff[(j * CN + c) * 9 + k];
    }
    __syncthreads();

    int p  = blockIdx.x * 256 + threadIdx.x;
    int b  = p >> 14;
    int hw = p & (SN - 1);
    int h  = hw >> 7;
    int w  = hw & (WN - 1);

    bool hm = h > 0, hp = h < HN - 1, wm = w > 0, wp = w < WN - 1;

    float a0 = boff[0], a1 = boff[1];
    const float* xb = xin + (size_t)b * CN * SN;

    #pragma unroll 2
    for (int c = 0; c < CN; c++) {
        const float* xc = xb + c * SN + hw;
        float v[9];
        v[4] = xc[0];
        v[1] = hm ? xc[-WN] : 0.f;
        v[7] = hp ? xc[ WN] : 0.f;
        v[3] = wm ? xc[-1] : 0.f;
        v[5] = wp ? xc[ 1] : 0.f;
        v[0] = (hm && wm) ? xc[-WN - 1] : 0.f;
        v[2] = (hm && wp) ? xc[-WN + 1] : 0.f;
        v[6] = (hp && wm) ? xc[ WN - 1] : 0.f;
        v[8] = (hp && wp) ? xc[ WN + 1] : 0.f;
        const float* wc = sw + c * 18;
        #pragma unroll
        for (int k = 0; k < 9; k++) {
            a0 += v[k] * wc[k * 2 + 0];
            a1 += v[k] * wc[k * 2 + 1];
        }
    }

    float lo   = (float)(*p_lo);
    float span = (float)(*p_hi) - lo;
    float s0 = 1.f / (1.f + __expf(-a0));
    float s1 = 1.f / (1.f + __expf(-a1));
    rfh[p] = 0.5f * (lo + span * s0);
    rfw[p] = 0.5f * (lo + span * s1);
}

// ---------------------------------------------------------------------------
// Warp-specialized mma.sync ARConv. 512 threads:
//   warps 0-7  = consumers: warp w -> px rows [32*(w&3),+32), o [32*(w>>2),+32)
//   warps 8-15 = producers: 2 threads/px x 32 channels, fill A ring (2 bufs)
// Handshake: named barriers full{0,1}=1,2 / empty{0,1}=3,4, count 512.
// ---------------------------------------------------------------------------
__global__ __launch_bounds__(512, 1)
void arconv_mma(const float* __restrict__ xin,
                const float* __restrict__ rfh, const float* __restrict__ rfw,
                const float* __restrict__ Wk,      // [O][C][3][3]
                const float* __restrict__ bias,    // [O]
                const float* __restrict__ resid,   // NCHW (mode 1) or null
                float* __restrict__ outp,
                int mode)
{
    extern __shared__ char smem[];
    int tid = threadIdx.x, wid = tid >> 5, lid = tid & 31;

    // B hi/lo conversion into SW128-swizzled tap tiles [o rows x c cols]
    for (int d = tid; d < 9 * 64 * 64; d += 512) {
        int tap = d >> 12;
        int o   = (d >> 6) & 63;
        int c   = d & 63;
        float wv = Wk[(o * 64 + c) * 9 + tap];
        __nv_bfloat16 hb = __float2bfloat16(wv);
        float hf = __bfloat162float(hb);
        __nv_bfloat16 lb = __float2bfloat16(wv - hf);
        uint32_t s = tap * 8192 + swz((uint32_t)(o * 128 + c * 2));
        *(__nv_bfloat16*)(smem + B_HI_OFF + s) = hb;
        *(__nv_bfloat16*)(smem + B_LO_OFF + s) = lb;
    }
    if (tid < 64) *(float*)(smem + BIAS_OFF + tid * 4) = bias[tid];
    __syncthreads();   // last block-wide barrier before role split

    const float* biasS = (const float*)(smem + BIAS_OFF);

    if (tid < 256) {
        // =================== CONSUMERS (warps 0-7) ===================
        int g = lid >> 2, t = lid & 3;
        int ohalf = wid >> 2;            // 0/1 : 32-o half
        int rbase = 32 * (wid & 3);      // px row base (32 rows)
        int gidx = 0;

        for (int it = 0; it < 4; it++) {
            int tile = blockIdx.x * 4 + it;
            int p0 = tile * 128;

            float acc[2][4][4];
            #pragma unroll
            for (int mr = 0; mr < 2; mr++)
                #pragma unroll
                for (int nb = 0; nb < 4; nb++)
                    #pragma unroll
                    for (int j = 0; j < 4; j++) acc[mr][nb][j] = 0.f;

            #pragma unroll 1
            for (int tap = 0; tap < 9; tap++) {
                int buf = gidx & 1;
                BAR_SYNC(1 + buf);       // wait full

                const char* Ch = smem + A_BASE + buf * 32768;
                const char* Cl = Ch + 16384;
                uint32_t btap = tap * 8192;

                #pragma unroll
                for (int chunk = 0; chunk < 4; chunk++) {
                    int ck = chunk * 16;
                    uint32_t ah[2][4], al[2][4];
                    #pragma unroll
                    for (int mr = 0; mr < 2; mr++) {
                        int r0 = rbase + 16 * mr + g;
                        uint32_t ar0 = swz((uint32_t)(r0 * 128 + (ck + 2 * t) * 2));
                        uint32_t ar1 = swz((uint32_t)((r0 + 8) * 128 + (ck + 2 * t) * 2));
                        uint32_t ac0 = swz((uint32_t)(r0 * 128 + (ck + 2 * t + 8) * 2));
                        uint32_t ac1 = swz((uint32_t)((r0 + 8) * 128 + (ck + 2 * t + 8) * 2));
                        ah[mr][0] = *(const uint32_t*)(Ch + ar0);
                        ah[mr][1] = *(const uint32_t*)(Ch + ar1);
                        ah[mr][2] = *(const uint32_t*)(Ch + ac0);
                        ah[mr][3] = *(const uint32_t*)(Ch + ac1);
                        al[mr][0] = *(const uint32_t*)(Cl + ar0);
                        al[mr][1] = *(const uint32_t*)(Cl + ar1);
                        al[mr][2] = *(const uint32_t*)(Cl + ac0);
                        al[mr][3] = *(const uint32_t*)(Cl + ac1);
                    }
                    #pragma unroll
                    for (int nb = 0; nb < 4; nb++) {
                        int o = ohalf * 32 + nb * 8 + g;
                        uint32_t br0 = swz((uint32_t)(o * 128 + (ck + 2 * t) * 2));
                        uint32_t br1 = swz((uint32_t)(o * 128 + (ck + 2 * t + 8) * 2));
                        uint32_t wh0 = *(const uint32_t*)(smem + B_HI_OFF + btap + br0);
                        uint32_t wh1 = *(const uint32_t*)(smem + B_HI_OFF + btap + br1);
                        uint32_t wl0 = *(const uint32_t*)(smem + B_LO_OFF + btap + br0);
                        uint32_t wl1 = *(const uint32_t*)(smem + B_LO_OFF + btap + br1);
                        #pragma unroll
                        for (int mr = 0; mr < 2; mr++) {
                            mma_bf16(acc[mr][nb][0], acc[mr][nb][1], acc[mr][nb][2], acc[mr][nb][3],
                                     ah[mr][0], ah[mr][1], ah[mr][2], ah[mr][3], wh0, wh1);
                            mma_bf16(acc[mr][nb][0], acc[mr][nb][1], acc[mr][nb][2], acc[mr][nb][3],
                                     al[mr][0], al[mr][1], al[mr][2], al[mr][3], wh0, wh1);
                            mma_bf16(acc[mr][nb][0], acc[mr][nb][1], acc[mr][nb][2], acc[mr][nb][3],
                                     ah[mr][0], ah[mr][1], ah[mr][2], ah[mr][3], wl0, wl1);
                        }
                    }
                }
                BAR_ARRIVE(3 + buf);     // signal empty
                gidx++;
            }

            // ---- epilogue: D fragments -> NCHW (overlaps next tile's produce)
            #pragma unroll
            for (int mr = 0; mr < 2; mr++) {
                int px0 = p0 + rbase + 16 * mr + g;
                int px1 = px0 + 8;
                int b0i = px0 >> 14, hw0 = px0 & (SN - 1);
                int b1i = px1 >> 14, hw1 = px1 & (SN - 1);
                #pragma unroll
                for (int nb = 0; nb < 4; nb++) {
                    int o0 = ohalf * 32 + nb * 8 + 2 * t;
                    int o1 = o0 + 1;
                    size_t i00 = ((size_t)(b0i * CN + o0)) * SN + hw0;
                    size_t i01 = ((size_t)(b0i * CN + o1)) * SN + hw0;
                    size_t i10 = ((size_t)(b1i * CN + o0)) * SN + hw1;
                    size_t i11 = ((size_t)(b1i * CN + o1)) * SN + hw1;
                    float v00 = acc[mr][nb][0] + biasS[o0];
                    float v01 = acc[mr][nb][1] + biasS[o1];
                    float v10 = acc[mr][nb][2] + biasS[o0];
                    float v11 = acc[mr][nb][3] + biasS[o1];
                    if (mode == 0) {
                        outp[i00] = fmaxf(v00, 0.f);
                        outp[i01] = fmaxf(v01, 0.f);
                        outp[i10] = fmaxf(v10, 0.f);
                        outp[i11] = fmaxf(v11, 0.f);
                    } else {
                        outp[i00] = v00 + resid[i00];
                        outp[i01] = v01 + resid[i01];
                        outp[i10] = v10 + resid[i10];
                        outp[i11] = v11 + resid[i11];
                    }
                }
            }
        }
    } else {
        // =================== PRODUCERS (warps 8-15) ===================
        int ptid = tid - 256;
        int px = ptid & 127;
        int cbase = (ptid >> 7) * 32;    // 2 threads/px, 32 channels each
        int gidx = 0;

        for (int it = 0; it < 4; it++) {
            int tile = blockIdx.x * 4 + it;
            int p = tile * 128 + px;
            int b = p >> 14;
            int hw = p & (SN - 1);
            int h = hw >> 7;
            int w = hw & (WN - 1);

            float rh = rfh[p];
            float rw = rfw[p];

            float xsl = (float)w - rw, xsr = (float)w + rw;
            float xl0f = floorf(xsl), xr0f = floorf(xsr);
            float txl = xsl - xl0f, txr = xsr - xr0f;
            int xl0 = min(max((int)xl0f, 0), WN - 1); int xl1 = min(xl0 + 1, WN - 1);
            int xr0 = min(max((int)xr0f, 0), WN - 1); int xr1 = min(xr0 + 1, WN - 1);

            float ysa = (float)h - rh, ysb = (float)h + rh;
            float ya0f = floorf(ysa), yb0f = floorf(ysb);
            float tya = ysa - ya0f, tyb = ysb - yb0f;
            int ya0 = min(max((int)ya0f, 0), HN - 1); int ya1 = min(ya0 + 1, HN - 1);
            int yb0 = min(max((int)yb0f, 0), HN - 1); int yb1 = min(yb0 + 1, HN - 1);

            int oa0 = ya0 * WN, oa1 = ya1 * WN, ohh = h * WN, ob0 = yb0 * WN, ob1 = yb1 * WN;

            const float* xb = xin + (size_t)(b * CN + cbase) * SN;

            #pragma unroll 1
            for (int tap = 0; tap < 9; tap++) {
                int ky = (tap >= 6) ? 2 : (tap >= 3) ? 1 : 0;
                int kx = tap - ky * 3;
                int ry0 = (ky == 0) ? oa0 : (ky == 1) ? ohh : ob0;
                int ry1 = (ky == 0) ? oa1 : (ky == 1) ? ohh : ob1;
                float tyv = (ky == 0) ? tya : (ky == 1) ? 0.f : tyb;
                int x0 = (kx == 0) ? xl0 : (kx == 1) ? w : xr0;
                int x1 = (kx == 0) ? xl1 : (kx == 1) ? w : xr1;
                float txv = (kx == 0) ? txl : (kx == 1) ? 0.f : txr;
                bool cy = (ky == 1), cx = (kx == 1);

                int buf = gidx & 1;
                if (gidx >= 2) BAR_SYNC(3 + buf);   // wait empty

                char* Ah = smem + A_BASE + buf * 32768;
                char* Al = Ah + 16384;

                #pragma unroll 1
                for (int cg = 0; cg < 4; cg++) {
                    const float* xc = xb + (size_t)(cg * 8) * SN;
                    float v[8];
                    if (cy && cx) {
                        #pragma unroll
                        for (int j = 0; j < 8; j++) v[j] = xc[(size_t)j * SN + ohh + w];
                    } else if (cy) {
                        float q0[8], q1[8];
                        #pragma unroll
                        for (int j = 0; j < 8; j++) {
                            q0[j] = xc[(size_t)j * SN + ohh + x0];
                            q1[j] = xc[(size_t)j * SN + ohh + x1];
                        }
                        #pragma unroll
                        for (int j = 0; j < 8; j++) v[j] = fmaf(txv, q1[j] - q0[j], q0[j]);
                    } else if (cx) {
                        float q0[8], q1[8];
                        #pragma unroll
                        for (int j = 0; j < 8; j++) {
                            q0[j] = xc[(size_t)j * SN + ry0 + w];
                            q1[j] = xc[(size_t)j * SN + ry1 + w];
                        }
                        #pragma unroll
                        for (int j = 0; j < 8; j++) v[j] = fmaf(tyv, q1[j] - q0[j], q0[j]);
                    } else {
                        float a0[8], a1[8], c0[8], c1[8];
                        #pragma unroll
                        for (int j = 0; j < 8; j++) {
                            a0[j] = xc[(size_t)j * SN + ry0 + x0];
                            a1[j] = xc[(size_t)j * SN + ry0 + x1];
                            c0[j] = xc[(size_t)j * SN + ry1 + x0];
                            c1[j] = xc[(size_t)j * SN + ry1 + x1];
                        }
                        #pragma unroll
                        for (int j = 0; j < 8; j++) {
                            float t0 = fmaf(txv, a1[j] - a0[j], a0[j]);
                            float t1 = fmaf(txv, c1[j] - c0[j], c0[j]);
                            v[j] = fmaf(tyv, t1 - t0, t0);
                        }
                    }

                    float hf[8], lo[8];
                    #pragma unroll
                    for (int j = 0; j < 8; j++) {
                        __nv_bfloat16 hb = __float2bfloat16(v[j]);
                        hf[j] = __bfloat162float(hb);
                        lo[j] = v[j] - hf[j];
                    }
                    uint4 HV, LV;
                    HV.x = pk2(hf[0], hf[1]); HV.y = pk2(hf[2], hf[3]);
                    HV.z = pk2(hf[4], hf[5]); HV.w = pk2(hf[6], hf[7]);
                    LV.x = pk2(lo[0], lo[1]); LV.y = pk2(lo[2], lo[3]);
                    LV.z = pk2(lo[4], lo[5]); LV.w = pk2(lo[6], lo[7]);

                    uint32_t s = swz((uint32_t)(px * 128 + (cbase + cg * 8) * 2));
                    *(uint4*)(Ah + s) = HV;
                    *(uint4*)(Al + s) = LV;
                }

                BAR_ARRIVE(1 + buf);     // signal full
                gidx++;
            }
        }
    }
}

// ---------------------------------------------------------------------------
extern "C" void kernel_launch(void* const* d_in, const int* in_sizes, int n_in,
                              void* d_out, int out_size)
{
    const float* x     = (const float*)d_in[0];
    const float* woff1 = (const float*)d_in[1];
    const float* boff1 = (const float*)d_in[2];
    const float* W1    = (const float*)d_in[3];
    const float* b1    = (const float*)d_in[4];
    const float* woff2 = (const float*)d_in[5];
    const float* boff2 = (const float*)d_in[6];
    const float* W2    = (const float*)d_in[7];
    const float* b2    = (const float*)d_in[8];
    const int*   lo    = (const int*)d_in[10];
    const int*   hi    = (const int*)d_in[11];
    float* out = (float*)d_out;

    float *y1, *rfh, *rfw;
    cudaGetSymbolAddress((void**)&y1,  g_y1);
    cudaGetSymbolAddress((void**)&rfh, g_rfh);
    cudaGetSymbolAddress((void**)&rfw, g_rfw);

    cudaFuncSetAttribute(arconv_mma, cudaFuncAttributeMaxDynamicSharedMemorySize, SMEM_TOTAL);

    // Layer 1
    offset_conv<<<NP / 256, 256>>>(x, woff1, boff1, lo, hi, rfh, rfw);
    arconv_mma<<<128, 512, SMEM_TOTAL>>>(x, rfh, rfw, W1, b1, nullptr, y1, 0);

    // Layer 2 (+ residual)
    offset_conv<<<NP / 256, 256>>>(y1, woff2, boff2, lo, hi, rfh, rfw);
    arconv_mma<<<128, 512, SMEM_TOTAL>>>(y1, rfh, rfw, W2, b2, x, out, 1);
}